// round 10
// baseline (speedup 1.0000x reference)
#include <cuda_runtime.h>
#include <cuda_bf16.h>
#include <cstdint>

#define NB 256
#define NS 2048
#define NK 64
#define LN2F 0.69314718055994531f
#define NBLK 148
#define WPB 11            // warps per block (352 threads)
#define NWCH 1536         // chain warps: 6 per batch
#define NWGOLD (NBLK * WPB - NWCH)   // 92 gold warps

// Scratch (device globals — no allocation allowed)
__device__ float g_vecA[NB][NK];    // A_511  (true fwd, rows 0..511)
__device__ float g_vecF1[NB][NK];   // f1 = 1^T M2 (rows 512..1023)
__device__ float g_vecF2[NB][NK];   // f2 = 1^T M3 (rows 1024..1535)
__device__ float g_vecG1[NB][NK];   // g1 = M2 1
__device__ float g_vecG2[NB][NK];   // g2 = M3 1
__device__ float g_vecB[NB][NK];    // beta (true bwd, rows 1536..2047)
__device__ float g_offA[NB];
__device__ float g_offG1[NB];
__device__ float g_offG2[NB];
__device__ float g_offB[NB];
__device__ float g_gold[NB];
__device__ unsigned g_done;         // zero-init; reset by last block each launch

typedef __nv_bfloat162 bf2;

__device__ __forceinline__ bf2 u2b(unsigned u) { return *reinterpret_cast<bf2*>(&u); }
__device__ __forceinline__ unsigned b2u(bf2 v) { return *reinterpret_cast<unsigned*>(&v); }

// matvec: z[2l..2l+1] = sum_i a[i] * E[i][2l..2l+1]
// 16x LDS.128 (broadcast, conflict-free) + 64x HFMA2 (rt 2), 4 acc chains.
__device__ __forceinline__ bf2 mv(const bf2* __restrict__ s, const unsigned (&Er)[NK]) {
    const uint4* q = (const uint4*)s;
    bf2 c0 = __floats2bfloat162_rn(0.f, 0.f);
    bf2 c1 = c0, c2 = c0, c3 = c0;
    #pragma unroll
    for (int g = 0; g < 16; g++) {
        uint4 v = q[g];
        c0 = __hfma2(u2b(v.x), u2b(Er[4 * g + 0]), c0);
        c1 = __hfma2(u2b(v.y), u2b(Er[4 * g + 1]), c1);
        c2 = __hfma2(u2b(v.z), u2b(Er[4 * g + 2]), c2);
        c3 = __hfma2(u2b(v.w), u2b(Er[4 * g + 3]), c3);
    }
    return __hadd2(__hadd2(c0, c1), __hadd2(c2, c3));
}

// Store (v.lo,v.lo),(v.hi,v.hi) dup-pairs as one STS.64 (2 PRMT + 1 STS).
__device__ __forceinline__ void store_dup(bf2* dst, bf2 v) {
    unsigned u = b2u(v);
    uint2 d;
    d.x = __byte_perm(u, u, 0x1010);
    d.y = __byte_perm(u, u, 0x3232);
    *reinterpret_cast<uint2*>(dst) = d;
}

// Exact power-of-two rescale (warp max via 5 shfl), offset in log domain.
__device__ __forceinline__ void rescale(bf2& v, float& off) {
    bf2 m2 = v;
    #pragma unroll
    for (int d = 16; d; d >>= 1)
        m2 = __hmax2(m2, u2b(__shfl_xor_sync(0xffffffffu, b2u(m2), d)));
    float m = fmaxf(__low2float(m2), __high2float(m2));
    int k = (__float_as_int(m) >> 23) - 127;
    k = k < -120 ? -120 : (k > 120 ? 120 : k);
    float scl = __int_as_float((127 - k) << 23);   // 2^-k (exact in bf16)
    v = __hmul2(v, __floats2bfloat162_rn(scl, scl));
    off += (float)k * LN2F;
}

// ---- forward step: matvec(read P) -> *exp(score) -> store P^1 ----
#define FSTEP(P, BUF) do {                                              \
    bf2 c_ = mv(myd[P], Er);                                            \
    float2 sv_ = BUF; BUF = *pre; pre += 32;                            \
    bf2 e_ = __floats2bfloat162_rn(__expf(sv_.x), __expf(sv_.y));       \
    av = __hmul2(c_, e_);                                               \
    store_dup(&myd[P ^ 1][2 * l], av);                                  \
    __syncwarp();                                                       \
} while (0)

#define FSTEP_R(P, BUF) do {                                            \
    bf2 c_ = mv(myd[P], Er);                                            \
    float2 sv_ = BUF; BUF = *pre; pre += 32;                            \
    bf2 e_ = __floats2bfloat162_rn(__expf(sv_.x), __expf(sv_.y));       \
    av = __hmul2(c_, e_);                                               \
    rescale(av, off);                                                   \
    store_dup(&myd[P ^ 1][2 * l], av);                                  \
    __syncwarp();                                                       \
} while (0)

// ---- backward step: w = av*exp(score) -> store P -> matvec(read P) ----
#define BSTEP(P, BUF) do {                                              \
    float2 sv_ = BUF; BUF = *pre; pre -= 32;                            \
    bf2 e_ = __floats2bfloat162_rn(__expf(sv_.x), __expf(sv_.y));       \
    bf2 w_ = __hmul2(av, e_);                                           \
    store_dup(&myd[P][2 * l], w_);                                      \
    __syncwarp();                                                       \
    av = mv(myd[P], Er);                                                \
} while (0)

#define BSTEP_R(P, BUF) do {                                            \
    float2 sv_ = BUF; BUF = *pre; pre -= 32;                            \
    bf2 e_ = __floats2bfloat162_rn(__expf(sv_.x), __expf(sv_.y));       \
    bf2 w_ = __hmul2(av, e_);                                           \
    rescale(w_, off);                                                   \
    store_dup(&myd[P][2 * l], w_);                                      \
    __syncwarp();                                                       \
    av = mv(myd[P], Er);                                                \
} while (0)

// 148 blocks x 11 warps = 1628 warp slots, exactly 1 block/SM.
//  gid in [0,1536): chain warps — batch = gid/6, role = gid%6:
//    role0: A    (true fwd,  rows 1..511,      511 steps, seed source+s0, off)
//    role1: f1   (fwd ones,  rows 512..1023,   512 steps, off cancels)
//    role2: f2   (fwd ones,  rows 1024..1535,  512 steps, off cancels)
//    role3: g1   (bwd ones,  rows 1023..512,   512 steps, off)
//    role4: g2   (bwd ones,  rows 1535..1024,  512 steps, off)
//    role5: beta (true bwd,  rows 2047..1536,  512 steps, seed sink, off)
//  gid in [1536,1628): gold-path warps (batches strided by NWGOLD).
// Last block to finish computes the final loss.
__global__ void __launch_bounds__(32 * WPB, 1)
crf_fused(const float* __restrict__ scores, const int* __restrict__ states,
          const float* __restrict__ trans, const float* __restrict__ source,
          const float* __restrict__ sink, float* __restrict__ out)
{
    __shared__ bf2 adup[WPB][2][NK];   // [warp][double-buffer][dup bf16x2]
    __shared__ float red[256];
    __shared__ int s_last;

    const int w = threadIdx.x >> 5;
    const int l = threadIdx.x & 31;
    const int gid = blockIdx.x * WPB + w;

    if (gid >= NWCH) {
        // ---------------- gold path (2-3 batches per warp) ----------------
        for (int b = gid - NWCH; b < NB; b += NWGOLD) {
            const int* st = states + b * NS;
            const float* sc = scores + (size_t)b * NS * NK;
            float acc = 0.f;
            #pragma unroll 4
            for (int t = l; t < NS; t += 32) {
                int s = st[t];
                float e = sc[t * NK + s];
                float tr = (t + 1 < NS) ? trans[s * NK + st[t + 1]] : 0.f;
                acc += e + tr;
            }
            #pragma unroll
            for (int d = 16; d; d >>= 1) acc += __shfl_xor_sync(0xffffffffu, acc, d);
            if (l == 0) g_gold[b] = acc + source[st[0]] + sink[st[NS - 1]];
        }
    } else {
        // ---------------- one segment-chain per warp ----------------
        const int b = gid / 6;
        const int role = gid % 6;
        const bool fwd = role < 3;
        bf2 (*myd)[NK] = adup[w];

        // Er: exp(transition) in bf16x2 (column pair for fwd, row pair for bwd).
        unsigned Er[NK];
        if (fwd) {
            #pragma unroll
            for (int i = 0; i < NK; i++) {
                float2 tv = ((const float2*)(trans + i * NK))[l];
                Er[i] = b2u(__floats2bfloat162_rn(expf(tv.x), expf(tv.y)));
            }
        } else {
            #pragma unroll
            for (int j = 0; j < NK; j++) {
                Er[j] = b2u(__floats2bfloat162_rn(expf(trans[(2 * l) * NK + j]),
                                                  expf(trans[(2 * l + 1) * NK + j])));
            }
        }

        const float2* pre0 = (const float2*)(scores + (size_t)b * NS * NK) + l;
        float off = 0.f;
        bf2 av;

        if (fwd) {
            int base;   // first consumed score row
            if (role == 0) {
                // alpha_0 = exp(source + scores[b,0,:])
                float2 s0 = pre0[0];
                float2 sr = ((const float2*)source)[l];
                av = __floats2bfloat162_rn(expf(sr.x + s0.x), expf(sr.y + s0.y));
                base = 1;
            } else {
                av = __floats2bfloat162_rn(1.f, 1.f);
                base = (role == 1) ? 512 : 1024;
            }
            store_dup(&myd[0][2 * l], av);
            __syncwarp();

            // depth-8 prefetch ring
            float2 f0 = pre0[(base + 0) * 32], f1 = pre0[(base + 1) * 32];
            float2 f2 = pre0[(base + 2) * 32], f3 = pre0[(base + 3) * 32];
            float2 f4 = pre0[(base + 4) * 32], f5 = pre0[(base + 5) * 32];
            float2 f6 = pre0[(base + 6) * 32], f7 = pre0[(base + 7) * 32];
            const float2* pre = pre0 + (base + 8) * 32;

            // 63 groups of 8 + 7 tail = 511 steps; roles 1/2 take one more.
            // Prefetch excursion <= base+519 <= 1543, in bounds.
            #pragma unroll 1
            for (int grp = 0; grp < 63; grp++) {
                FSTEP(0, f0); FSTEP(1, f1); FSTEP(0, f2); FSTEP(1, f3);
                FSTEP(0, f4); FSTEP(1, f5); FSTEP(0, f6); FSTEP_R(1, f7);
            }
            FSTEP(0, f0); FSTEP(1, f1); FSTEP(0, f2); FSTEP(1, f3);
            FSTEP(0, f4); FSTEP(1, f5); FSTEP(0, f6);
            if (role != 0) { FSTEP(1, f7); }   // step 512 for f1/f2

            rescale(av, off);   // final peg
            float* dst = (role == 0) ? g_vecA[b] : (role == 1) ? g_vecF1[b] : g_vecF2[b];
            dst[2 * l]     = __low2float(av);
            dst[2 * l + 1] = __high2float(av);
            if (l == 0 && role == 0) g_offA[b] = off;   // f offsets cancel
        } else {
            int base;   // first consumed score row (descending)
            if (role == 5) {
                float2 sk = ((const float2*)sink)[l];
                av = __floats2bfloat162_rn(expf(sk.x), expf(sk.y));
                base = 2047;
            } else {
                av = __floats2bfloat162_rn(1.f, 1.f);
                base = (role == 3) ? 1023 : 1535;
            }

            // depth-8 prefetch ring (descending)
            float2 f0 = pre0[(base - 0) * 32], f1 = pre0[(base - 1) * 32];
            float2 f2 = pre0[(base - 2) * 32], f3 = pre0[(base - 3) * 32];
            float2 f4 = pre0[(base - 4) * 32], f5 = pre0[(base - 5) * 32];
            float2 f6 = pre0[(base - 6) * 32], f7 = pre0[(base - 7) * 32];
            const float2* pre = pre0 + (base - 8) * 32;

            // 64 groups of 8 = 512 steps. Prefetch >= base-519 >= 504, in bounds.
            #pragma unroll 1
            for (int grp = 0; grp < 64; grp++) {
                BSTEP(0, f0); BSTEP(1, f1); BSTEP(0, f2); BSTEP(1, f3);
                BSTEP(0, f4); BSTEP(1, f5); BSTEP(0, f6); BSTEP_R(1, f7);
            }

            rescale(av, off);   // final peg
            float* dst = (role == 3) ? g_vecG1[b] : (role == 4) ? g_vecG2[b] : g_vecB[b];
            dst[2 * l]     = __low2float(av);
            dst[2 * l + 1] = __high2float(av);
            if (l == 0) {
                if (role == 3) g_offG1[b] = off;
                else if (role == 4) g_offG2[b] = off;
                else g_offB[b] = off;
            }
        }
    }

    // ---------------- completion: last block reduces ----------------
    __syncthreads();
    if (threadIdx.x == 0) {
        __threadfence();
        s_last = (atomicAdd(&g_done, 1u) == NBLK - 1u) ? 1 : 0;
    }
    __syncthreads();
    if (!s_last) return;
    __threadfence();

    // loss_b = log(A.g1) + log(f1.g2) + log(f2.beta) - log(f1.1) - log(f2.1)
    //        + offA + offG1 + offG2 + offB - gold
    const int b = threadIdx.x;
    if (b < NB) {
        float dA = 0.f, d12 = 0.f, d2B = 0.f, n1 = 0.f, n2 = 0.f;
        #pragma unroll 4
        for (int j = 0; j < NK; j++) {
            float f1j = g_vecF1[b][j], f2j = g_vecF2[b][j];
            dA  += g_vecA[b][j] * g_vecG1[b][j];
            d12 += f1j * g_vecG2[b][j];
            d2B += f2j * g_vecB[b][j];
            n1  += f1j;
            n2  += f2j;
        }
        red[b] = logf(dA) + logf(d12) + logf(d2B) - logf(n1) - logf(n2)
               + g_offA[b] + g_offG1[b] + g_offG2[b] + g_offB[b] - g_gold[b];
    }
    __syncthreads();
    #pragma unroll
    for (int k = 128; k; k >>= 1) {
        if (threadIdx.x < k && threadIdx.x + k < NB + k && threadIdx.x < NB)
            if (threadIdx.x + k < NB || k >= NB) {}   // (guards folded below)
        __syncthreads();
    }
    // simple serial-safe reduction (256 values, first warp finishes it)
    if (threadIdx.x < 32) {
        float s = 0.f;
        for (int i = threadIdx.x; i < NB; i += 32) s += red[i];
        #pragma unroll
        for (int d = 16; d; d >>= 1) s += __shfl_xor_sync(0xffffffffu, s, d);
        if (threadIdx.x == 0) { out[0] = s * (1.0f / NB); g_done = 0; }
    }
}

extern "C" void kernel_launch(void* const* d_in, const int* in_sizes, int n_in,
                              void* d_out, int out_size)
{
    const float* scores = (const float*)d_in[0];
    const int*   states = (const int*)d_in[1];
    const float* trans  = (const float*)d_in[2];
    const float* source = (const float*)d_in[3];
    const float* sink   = (const float*)d_in[4];

    crf_fused<<<NBLK, 32 * WPB>>>(scores, states, trans, source, sink, (float*)d_out);
}

// round 11
// speedup vs baseline: 1.0430x; 1.0430x over previous
#include <cuda_runtime.h>
#include <cuda_bf16.h>
#include <cstdint>

#define NB 256
#define NS 2048
#define NK 64
#define LN2F 0.69314718055994531f
#define NBLK 148
#define WPB 11            // warps per block (352 threads)
#define NWCH 1536         // chain warps: 6 per batch
#define NWGOLD (NBLK * WPB - NWCH)   // 92 gold warps

// Scratch (device globals — no allocation allowed)
__device__ float g_vecA[NB][NK];    // A_511  (true fwd, rows 0..511)
__device__ float g_vecF1[NB][NK];   // f1 = 1^T M2 (rows 512..1023)
__device__ float g_vecF2[NB][NK];   // f2 = 1^T M3 (rows 1024..1535)
__device__ float g_vecG1[NB][NK];   // g1 = M2 1
__device__ float g_vecG2[NB][NK];   // g2 = M3 1
__device__ float g_vecB[NB][NK];    // beta (true bwd, rows 1536..2047)
__device__ float g_offA[NB];
__device__ float g_offG1[NB];
__device__ float g_offG2[NB];
__device__ float g_offB[NB];
__device__ float g_gold[NB];
__device__ unsigned g_done;         // zero-init; reset by last block each launch

typedef __nv_bfloat162 bf2;

__device__ __forceinline__ bf2 u2b(unsigned u) { return *reinterpret_cast<bf2*>(&u); }
__device__ __forceinline__ unsigned b2u(bf2 v) { return *reinterpret_cast<unsigned*>(&v); }

// matvec, plain-packed vector (lane i stored pair (a_2i, a_2i+1) as one bf2):
// 8x LDS.128 (128 B/lane/step — half the dup layout's crossbar bill) + 64x HFMA2.
// Ee[i2] = (E[2i2][c], E[2i2+1][c]) for this lane's even column c=2l;
// Eo[i2] = same for odd column 2l+1. lo/hi of each accumulator carry the
// even-i / odd-i partials; folded in fp32 at the end.
__device__ __forceinline__ void mv2(const bf2* __restrict__ s,
                                    const unsigned (&Ee)[32], const unsigned (&Eo)[32],
                                    float& zl, float& zh) {
    const uint4* q = (const uint4*)s;
    bf2 zz = __floats2bfloat162_rn(0.f, 0.f);
    bf2 ce0 = zz, ce1 = zz, co0 = zz, co1 = zz;
    #pragma unroll
    for (int g = 0; g < 8; g++) {
        uint4 v = q[g];
        ce0 = __hfma2(u2b(v.x), u2b(Ee[4 * g + 0]), ce0);
        co0 = __hfma2(u2b(v.x), u2b(Eo[4 * g + 0]), co0);
        ce1 = __hfma2(u2b(v.y), u2b(Ee[4 * g + 1]), ce1);
        co1 = __hfma2(u2b(v.y), u2b(Eo[4 * g + 1]), co1);
        ce0 = __hfma2(u2b(v.z), u2b(Ee[4 * g + 2]), ce0);
        co0 = __hfma2(u2b(v.z), u2b(Eo[4 * g + 2]), co0);
        ce1 = __hfma2(u2b(v.w), u2b(Ee[4 * g + 3]), ce1);
        co1 = __hfma2(u2b(v.w), u2b(Eo[4 * g + 3]), co1);
    }
    bf2 ce = __hadd2(ce0, ce1), co = __hadd2(co0, co1);
    zl = __low2float(ce) + __high2float(ce);
    zh = __low2float(co) + __high2float(co);
}

// Exact power-of-two rescale (warp max via 5 shfl), offset in log domain.
__device__ __forceinline__ void rescale(bf2& v, float& off) {
    bf2 m2 = v;
    #pragma unroll
    for (int d = 16; d; d >>= 1)
        m2 = __hmax2(m2, u2b(__shfl_xor_sync(0xffffffffu, b2u(m2), d)));
    float m = fmaxf(__low2float(m2), __high2float(m2));
    int k = (__float_as_int(m) >> 23) - 127;
    k = k < -120 ? -120 : (k > 120 ? 120 : k);
    float scl = __int_as_float((127 - k) << 23);   // 2^-k (exact in bf16)
    v = __hmul2(v, __floats2bfloat162_rn(scl, scl));
    off += (float)k * LN2F;
}

// ---- forward step: matvec(read P) -> *exp(score) -> store P^1 (plain STS.32) ----
#define FSTEP(P, BUF) do {                                              \
    float zl_, zh_; mv2(myd[P], Ee, Eo, zl_, zh_);                      \
    float2 sv_ = BUF; BUF = *pre; pre += 32;                            \
    av = __floats2bfloat162_rn(zl_ * __expf(sv_.x), zh_ * __expf(sv_.y)); \
    myd[P ^ 1][l] = av;                                                 \
    __syncwarp();                                                       \
} while (0)

#define FSTEP_R(P, BUF) do {                                            \
    float zl_, zh_; mv2(myd[P], Ee, Eo, zl_, zh_);                      \
    float2 sv_ = BUF; BUF = *pre; pre += 32;                            \
    av = __floats2bfloat162_rn(zl_ * __expf(sv_.x), zh_ * __expf(sv_.y)); \
    rescale(av, off);                                                   \
    myd[P ^ 1][l] = av;                                                 \
    __syncwarp();                                                       \
} while (0)

// ---- backward step: w = av*exp(score) -> store P -> matvec(read P) ----
#define BSTEP(P, BUF) do {                                              \
    float2 sv_ = BUF; BUF = *pre; pre -= 32;                            \
    bf2 e_ = __floats2bfloat162_rn(__expf(sv_.x), __expf(sv_.y));       \
    bf2 w_ = __hmul2(av, e_);                                           \
    myd[P][l] = w_;                                                     \
    __syncwarp();                                                       \
    float zl_, zh_; mv2(myd[P], Ee, Eo, zl_, zh_);                      \
    av = __floats2bfloat162_rn(zl_, zh_);                               \
} while (0)

#define BSTEP_R(P, BUF) do {                                            \
    float2 sv_ = BUF; BUF = *pre; pre -= 32;                            \
    bf2 e_ = __floats2bfloat162_rn(__expf(sv_.x), __expf(sv_.y));       \
    bf2 w_ = __hmul2(av, e_);                                           \
    rescale(w_, off);                                                   \
    myd[P][l] = w_;                                                     \
    __syncwarp();                                                       \
    float zl_, zh_; mv2(myd[P], Ee, Eo, zl_, zh_);                      \
    av = __floats2bfloat162_rn(zl_, zh_);                               \
} while (0)

// 148 blocks x 11 warps = 1628 warp slots, exactly 1 block/SM.
//  gid in [0,1536): chain warps — batch = gid/6, role = gid%6:
//    role0: A    (true fwd,  rows 1..511,      511 steps, seed source+s0, off)
//    role1: f1   (fwd ones,  rows 512..1023,   512 steps, off cancels)
//    role2: f2   (fwd ones,  rows 1024..1535,  512 steps, off cancels)
//    role3: g1   (bwd ones,  rows 1023..512,   512 steps, off)
//    role4: g2   (bwd ones,  rows 1535..1024,  512 steps, off)
//    role5: beta (true bwd,  rows 2047..1536,  512 steps, seed sink, off)
//  gid in [1536,1628): gold-path warps (batches strided by NWGOLD).
// Last block to finish computes the final loss.
__global__ void __launch_bounds__(32 * WPB, 1)
crf_fused(const float* __restrict__ scores, const int* __restrict__ states,
          const float* __restrict__ trans, const float* __restrict__ source,
          const float* __restrict__ sink, float* __restrict__ out)
{
    __shared__ bf2 vbuf[WPB][2][32];   // [warp][double-buffer][packed pair] 128B/buf
    __shared__ float red[256];
    __shared__ int s_last;

    const int w = threadIdx.x >> 5;
    const int l = threadIdx.x & 31;
    const int gid = blockIdx.x * WPB + w;

    if (gid >= NWCH) {
        // ---------------- gold path (2-3 batches per warp) ----------------
        for (int b = gid - NWCH; b < NB; b += NWGOLD) {
            const int* st = states + b * NS;
            const float* sc = scores + (size_t)b * NS * NK;
            float acc = 0.f;
            #pragma unroll 4
            for (int t = l; t < NS; t += 32) {
                int s = st[t];
                float e = sc[t * NK + s];
                float tr = (t + 1 < NS) ? trans[s * NK + st[t + 1]] : 0.f;
                acc += e + tr;
            }
            #pragma unroll
            for (int d = 16; d; d >>= 1) acc += __shfl_xor_sync(0xffffffffu, acc, d);
            if (l == 0) g_gold[b] = acc + source[st[0]] + sink[st[NS - 1]];
        }
    } else {
        // ---------------- one segment-chain per warp ----------------
        const int b = gid / 6;
        const int role = gid % 6;
        const bool fwd = role < 3;
        bf2 (*myd)[32] = vbuf[w];

        // E banks: lane's even column (2l) in Ee, odd column (2l+1) in Eo,
        // i packed in pairs to match the plain-packed vector layout.
        unsigned Ee[32], Eo[32];
        if (fwd) {
            // z[c] = sum_i a[i] E[i][c]
            #pragma unroll
            for (int i2 = 0; i2 < 32; i2++) {
                const float* r0 = trans + (2 * i2) * NK;
                const float* r1 = trans + (2 * i2 + 1) * NK;
                Ee[i2] = b2u(__floats2bfloat162_rn(expf(r0[2 * l]),     expf(r1[2 * l])));
                Eo[i2] = b2u(__floats2bfloat162_rn(expf(r0[2 * l + 1]), expf(r1[2 * l + 1])));
            }
        } else {
            // beta'[r] = sum_j E[r][j] w[j]; rows 2l (Ee) and 2l+1 (Eo), j-pairs packed.
            #pragma unroll
            for (int j2 = 0; j2 < 32; j2++) {
                float2 e0v = ((const float2*)(trans + (2 * l) * NK))[j2];
                float2 e1v = ((const float2*)(trans + (2 * l + 1) * NK))[j2];
                Ee[j2] = b2u(__floats2bfloat162_rn(expf(e0v.x), expf(e0v.y)));
                Eo[j2] = b2u(__floats2bfloat162_rn(expf(e1v.x), expf(e1v.y)));
            }
        }

        const float2* pre0 = (const float2*)(scores + (size_t)b * NS * NK) + l;
        float off = 0.f;
        bf2 av;

        if (fwd) {
            int base;   // first consumed score row
            if (role == 0) {
                // alpha_0 = exp(source + scores[b,0,:])
                float2 s0 = pre0[0];
                float2 sr = ((const float2*)source)[l];
                av = __floats2bfloat162_rn(expf(sr.x + s0.x), expf(sr.y + s0.y));
                base = 1;
            } else {
                av = __floats2bfloat162_rn(1.f, 1.f);
                base = (role == 1) ? 512 : 1024;
            }
            myd[0][l] = av;
            __syncwarp();

            // depth-8 prefetch ring
            float2 f0 = pre0[(base + 0) * 32], f1 = pre0[(base + 1) * 32];
            float2 f2 = pre0[(base + 2) * 32], f3 = pre0[(base + 3) * 32];
            float2 f4 = pre0[(base + 4) * 32], f5 = pre0[(base + 5) * 32];
            float2 f6 = pre0[(base + 6) * 32], f7 = pre0[(base + 7) * 32];
            const float2* pre = pre0 + (base + 8) * 32;

            // 63 groups of 8 + 7 tail = 511 steps; roles 1/2 take one more.
            // Prefetch excursion <= base+519 <= 1543, in bounds.
            #pragma unroll 1
            for (int grp = 0; grp < 63; grp++) {
                FSTEP(0, f0); FSTEP(1, f1); FSTEP(0, f2); FSTEP(1, f3);
                FSTEP(0, f4); FSTEP(1, f5); FSTEP(0, f6); FSTEP_R(1, f7);
            }
            FSTEP(0, f0); FSTEP(1, f1); FSTEP(0, f2); FSTEP(1, f3);
            FSTEP(0, f4); FSTEP(1, f5); FSTEP(0, f6);
            if (role != 0) { FSTEP(1, f7); }   // step 512 for f1/f2

            rescale(av, off);   // final peg
            float* dst = (role == 0) ? g_vecA[b] : (role == 1) ? g_vecF1[b] : g_vecF2[b];
            dst[2 * l]     = __low2float(av);
            dst[2 * l + 1] = __high2float(av);
            if (l == 0 && role == 0) g_offA[b] = off;   // f offsets cancel
        } else {
            int base;   // first consumed score row (descending)
            if (role == 5) {
                float2 sk = ((const float2*)sink)[l];
                av = __floats2bfloat162_rn(expf(sk.x), expf(sk.y));
                base = 2047;
            } else {
                av = __floats2bfloat162_rn(1.f, 1.f);
                base = (role == 3) ? 1023 : 1535;
            }

            // depth-8 prefetch ring (descending)
            float2 f0 = pre0[(base - 0) * 32], f1 = pre0[(base - 1) * 32];
            float2 f2 = pre0[(base - 2) * 32], f3 = pre0[(base - 3) * 32];
            float2 f4 = pre0[(base - 4) * 32], f5 = pre0[(base - 5) * 32];
            float2 f6 = pre0[(base - 6) * 32], f7 = pre0[(base - 7) * 32];
            const float2* pre = pre0 + (base - 8) * 32;

            // 64 groups of 8 = 512 steps. Prefetch >= base-519 >= 504, in bounds.
            #pragma unroll 1
            for (int grp = 0; grp < 64; grp++) {
                BSTEP(0, f0); BSTEP(1, f1); BSTEP(0, f2); BSTEP(1, f3);
                BSTEP(0, f4); BSTEP(1, f5); BSTEP(0, f6); BSTEP_R(1, f7);
            }

            rescale(av, off);   // final peg
            float* dst = (role == 3) ? g_vecG1[b] : (role == 4) ? g_vecG2[b] : g_vecB[b];
            dst[2 * l]     = __low2float(av);
            dst[2 * l + 1] = __high2float(av);
            if (l == 0) {
                if (role == 3) g_offG1[b] = off;
                else if (role == 4) g_offG2[b] = off;
                else g_offB[b] = off;
            }
        }
    }

    // ---------------- completion: last block reduces ----------------
    __syncthreads();
    if (threadIdx.x == 0) {
        __threadfence();
        s_last = (atomicAdd(&g_done, 1u) == NBLK - 1u) ? 1 : 0;
    }
    __syncthreads();
    if (!s_last) return;
    __threadfence();

    // loss_b = log(A.g1) + log(f1.g2) + log(f2.beta) - log(f1.1) - log(f2.1)
    //        + offA + offG1 + offG2 + offB - gold
    if (threadIdx.x < NB) {
        const int b = threadIdx.x;
        float dA = 0.f, d12 = 0.f, d2B = 0.f, n1 = 0.f, n2 = 0.f;
        #pragma unroll 4
        for (int j = 0; j < NK; j++) {
            float f1j = g_vecF1[b][j], f2j = g_vecF2[b][j];
            dA  += g_vecA[b][j] * g_vecG1[b][j];
            d12 += f1j * g_vecG2[b][j];
            d2B += f2j * g_vecB[b][j];
            n1  += f1j;
            n2  += f2j;
        }
        red[b] = logf(dA) + logf(d12) + logf(d2B) - logf(n1) - logf(n2)
               + g_offA[b] + g_offG1[b] + g_offG2[b] + g_offB[b] - g_gold[b];
    }
    __syncthreads();
    if (threadIdx.x < 32) {
        float s = 0.f;
        for (int i = threadIdx.x; i < NB; i += 32) s += red[i];
        #pragma unroll
        for (int d = 16; d; d >>= 1) s += __shfl_xor_sync(0xffffffffu, s, d);
        if (threadIdx.x == 0) { out[0] = s * (1.0f / NB); g_done = 0; }
    }
}

extern "C" void kernel_launch(void* const* d_in, const int* in_sizes, int n_in,
                              void* d_out, int out_size)
{
    const float* scores = (const float*)d_in[0];
    const int*   states = (const int*)d_in[1];
    const float* trans  = (const float*)d_in[2];
    const float* source = (const float*)d_in[3];
    const float* sink   = (const float*)d_in[4];

    crf_fused<<<NBLK, 32 * WPB>>>(scores, states, trans, source, sink, (float*)d_out);
}